// round 2
// baseline (speedup 1.0000x reference)
#include <cuda_runtime.h>

#define BATCH 8
#define NCH   6
#define HH    1024
#define WW    1024
#define TX    64
#define TY    32
#define HX    72      // aligned halo: [bx-4, bx+68)
#define HY    36      // [by-2, by+34)
#define CHUNKS 18     // HX / 4
#define CH_STRIDE4 (HH * WW / 4)
#define NPIX  (8.0f * 1024.0f * 1024.0f)

__device__ int g_tgt_is64;

// Zero output; detect int64 vs int32 targets (values in [0,5] => for int64 the
// odd 32-bit words of the first 256 elements are all zero; P(false positive
// for int32 data) = (1/6)^256 ~ 0).
__global__ void dcl_init_kernel(const int* __restrict__ tgt32, float* __restrict__ out) {
    if (threadIdx.x == 0) {
        int is64 = 1;
        for (int i = 0; i < 256; ++i)
            if (tgt32[2 * i + 1] != 0) { is64 = 0; break; }
        g_tgt_is64 = is64;
        *out = 0.0f;
    }
}

__global__ __launch_bounds__(256) void dcl_main(
    const float* __restrict__ pred,
    const void*  __restrict__ tgt,
    float* __restrict__ out)
{
    // Packed moment maps: p = v + (v*v << 8), v in [0,5].
    // 5-sum horizontal: s1<=25, s2<=125; vertical of those: s1<=125, s2<=625.
    // Fields never carry into each other.
    __shared__ unsigned raw_c[HY][HX];
    __shared__ unsigned raw_t[HY][HX];
    __shared__ unsigned h_c[HY][TX];
    __shared__ unsigned h_t[HY][TX];

    const int tid = threadIdx.x;
    const int bx  = blockIdx.x * TX;
    const int by  = blockIdx.y * TY;
    const int b   = blockIdx.z;

    const float*     p0   = pred + (size_t)b * NCH * HH * WW;
    const int        is64 = g_tgt_is64;
    const long long* tb64 = (const long long*)tgt + (size_t)b * HH * WW;
    const int*       tb32 = (const int*)tgt       + (size_t)b * HH * WW;

    // ---- Phase 1: vectorized load, argmax, pack ----
    for (int i = tid; i < HY * CHUNKS; i += 256) {
        const int r  = i / CHUNKS;
        const int ci = i - r * CHUNKS;
        const int gy = by + r - 2;
        const int gx = bx + ci * 4 - 4;    // float4-aligned (bx mult of 64)
        uint4 pc = make_uint4(0, 0, 0, 0);
        uint4 pt = make_uint4(0, 0, 0, 0);
        if ((unsigned)gy < (unsigned)HH && (unsigned)gx < (unsigned)WW) {
            const float4* pp = (const float4*)(p0 + (size_t)gy * WW + gx);
            float4 v[NCH];
            #pragma unroll
            for (int ch = 0; ch < NCH; ++ch) v[ch] = pp[(size_t)ch * CH_STRIDE4];

            int i0 = 0, i1 = 0, i2 = 0, i3 = 0;
            float m0 = v[0].x, m1 = v[0].y, m2 = v[0].z, m3 = v[0].w;
            #pragma unroll
            for (int ch = 1; ch < NCH; ++ch) {
                if (v[ch].x > m0) { m0 = v[ch].x; i0 = ch; }
                if (v[ch].y > m1) { m1 = v[ch].y; i1 = ch; }
                if (v[ch].z > m2) { m2 = v[ch].z; i2 = ch; }
                if (v[ch].w > m3) { m3 = v[ch].w; i3 = ch; }
            }
            pc.x = (unsigned)(i0 + ((i0 * i0) << 8));
            pc.y = (unsigned)(i1 + ((i1 * i1) << 8));
            pc.z = (unsigned)(i2 + ((i2 * i2) << 8));
            pc.w = (unsigned)(i3 + ((i3 * i3) << 8));

            int t0, t1, t2, t3;
            if (is64) {
                const int4* tp = (const int4*)(tb64 + (size_t)gy * WW + gx);
                int4 q0 = tp[0], q1 = tp[1];
                t0 = q0.x; t1 = q0.z; t2 = q1.x; t3 = q1.z;
            } else {
                int4 q = *(const int4*)(tb32 + (size_t)gy * WW + gx);
                t0 = q.x; t1 = q.y; t2 = q.z; t3 = q.w;
            }
            pt.x = (unsigned)(t0 + ((t0 * t0) << 8));
            pt.y = (unsigned)(t1 + ((t1 * t1) << 8));
            pt.z = (unsigned)(t2 + ((t2 * t2) << 8));
            pt.w = (unsigned)(t3 + ((t3 * t3) << 8));
        }
        *(uint4*)&raw_c[r][ci * 4] = pc;
        *(uint4*)&raw_t[r][ci * 4] = pt;
    }
    __syncthreads();

    // ---- Phase 2: horizontal 5-sums (packed integer adds) ----
    for (int i = tid; i < HY * TX; i += 256) {
        const int r = i >> 6;
        const int c = i & 63;
        h_c[r][c] = raw_c[r][c + 2] + raw_c[r][c + 3] + raw_c[r][c + 4]
                  + raw_c[r][c + 5] + raw_c[r][c + 6];
        h_t[r][c] = raw_t[r][c + 2] + raw_t[r][c + 3] + raw_t[r][c + 4]
                  + raw_t[r][c + 5] + raw_t[r][c + 6];
    }
    __syncthreads();

    // ---- Phase 3: vertical sliding 5-window, exact integer variance ----
    const int c  = tid & 63;
    const int r0 = (tid >> 6) * 8;     // 4 groups x 8 output rows
    unsigned sc = 0, st = 0;
    #pragma unroll
    for (int d = 0; d < 5; ++d) { sc += h_c[r0 + d][c]; st += h_t[r0 + d][c]; }

    float acc = 0.0f;
    #pragma unroll
    for (int rr = 0; rr < 8; ++rr) {
        const int s1c = (int)(sc & 255u), s2c = (int)(sc >> 8);
        const int s1t = (int)(st & 255u), s2t = (int)(st >> 8);
        const int nump = 25 * s2c - s1c * s1c;   // >= 0 exactly
        const int numt = 25 * s2t - s1t * s1t;
        const float d = sqrtf((float)nump * (1.0f / 600.0f))
                      - sqrtf((float)numt * (1.0f / 600.0f));
        acc = fmaf(d, d, acc);
        if (rr < 7) {
            sc += h_c[r0 + rr + 5][c] - h_c[r0 + rr][c];
            st += h_t[r0 + rr + 5][c] - h_t[r0 + rr][c];
        }
    }

    // ---- Reduce: warp shuffle -> smem -> one atomic per block ----
    acc *= (1.0f / NPIX);
    #pragma unroll
    for (int o = 16; o > 0; o >>= 1)
        acc += __shfl_down_sync(0xffffffffu, acc, o);

    __shared__ float warpsum[8];
    if ((tid & 31) == 0) warpsum[tid >> 5] = acc;
    __syncthreads();
    if (tid < 8) {
        float v = warpsum[tid];
        #pragma unroll
        for (int o = 4; o > 0; o >>= 1)
            v += __shfl_down_sync(0xffu, v, o);
        if (tid == 0) atomicAdd(out, v);
    }
}

extern "C" void kernel_launch(void* const* d_in, const int* in_sizes, int n_in,
                              void* d_out, int out_size) {
    const float* pred = (const float*)d_in[0];
    const void*  tgt  = d_in[1];
    float* out = (float*)d_out;

    dcl_init_kernel<<<1, 32>>>((const int*)tgt, out);

    dim3 grid(WW / TX, HH / TY, BATCH);
    dcl_main<<<grid, 256>>>(pred, tgt, out);
}

// round 4
// speedup vs baseline: 1.2338x; 1.2338x over previous
#include <cuda_runtime.h>

#define BATCH 8
#define NCH   6
#define HH    1024
#define WW    1024
#define TX    64
#define TY    32
#define HX    72      // halo cols: [bx-4, bx+68), 4-aligned
#define HY    36      // halo rows: [by-2, by+34)
#define CHUNKS 18     // HX/4
#define NPIX  (8.0f * 1024.0f * 1024.0f)
#define PIX_PER_B (HH * WW)          // 1<<20
#define CH_STRIDE4 (PIX_PER_B / 4)   // 262144

__device__ int g_tgt_is64;
__device__ unsigned g_code4[(BATCH * PIX_PER_B) / 4];   // 8 MiB: 4 packed bytes/word

// Zero output; detect int64 vs int32 targets (values in [0,5] => int64 odd
// words of first 256 elems are all zero; P(false pos for int32) = (1/6)^256).
__global__ void dcl_init(const int* __restrict__ tgt32, float* __restrict__ out) {
    const int lane = threadIdx.x;
    int nz = 0;
    #pragma unroll
    for (int i = lane; i < 256; i += 32) nz |= tgt32[2 * i + 1];
    const unsigned any = __ballot_sync(0xffffffffu, nz != 0);
    if (lane == 0) { g_tgt_is64 = (any == 0); *out = 0.0f; }
}

// ---- Kernel A: pure streaming argmax + pack (4 pixels/thread) ----
__global__ __launch_bounds__(256) void dcl_classify(
    const float* __restrict__ pred, const void* __restrict__ tgt)
{
    const unsigned t   = blockIdx.x * 256u + threadIdx.x;   // pixel4 index
    const unsigned b   = t >> 18;                           // 2^18 pixel4 per batch
    const unsigned off = t & 0x3FFFFu;

    const float4* pp = (const float4*)pred + (size_t)b * NCH * CH_STRIDE4 + off;
    float4 v[NCH];
    #pragma unroll
    for (int ch = 0; ch < NCH; ++ch) v[ch] = pp[(size_t)ch * CH_STRIDE4];

    int t0, t1, t2, t3;
    if (g_tgt_is64) {
        const int4* tp = (const int4*)tgt + (size_t)t * 2;
        const int4 q0 = tp[0], q1 = tp[1];
        t0 = q0.x; t1 = q0.z; t2 = q1.x; t3 = q1.z;
    } else {
        const int4 q = ((const int4*)tgt)[t];
        t0 = q.x; t1 = q.y; t2 = q.z; t3 = q.w;
    }

    int i0 = 0, i1 = 0, i2 = 0, i3 = 0;
    float m0 = v[0].x, m1 = v[0].y, m2 = v[0].z, m3 = v[0].w;
    #pragma unroll
    for (int ch = 1; ch < NCH; ++ch) {
        if (v[ch].x > m0) { m0 = v[ch].x; i0 = ch; }
        if (v[ch].y > m1) { m1 = v[ch].y; i1 = ch; }
        if (v[ch].z > m2) { m2 = v[ch].z; i2 = ch; }
        if (v[ch].w > m3) { m3 = v[ch].w; i3 = ch; }
    }

    const unsigned b0 = (unsigned)(i0 | (t0 << 4));
    const unsigned b1 = (unsigned)(i1 | (t1 << 4));
    const unsigned b2 = (unsigned)(i2 | (t2 << 4));
    const unsigned b3 = (unsigned)(i3 | (t3 << 4));
    g_code4[t] = b0 | (b1 << 8) | (b2 << 16) | (b3 << 24);
}

// ---- Kernel B: tiled separable 5x5 std stencil + MSE reduce ----
__global__ __launch_bounds__(256) void dcl_stencil(float* __restrict__ out)
{
    // Packed moments: m = v + (v*v << 8). Horizontal 5-sum: s1<=25, s2<=125;
    // vertical 5-sum of those: s1<=125 (8-bit field ok), s2<=625. Exact.
    __shared__ unsigned raw_c[HY][HX];
    __shared__ unsigned raw_t[HY][HX];
    __shared__ unsigned h_c[HY][TX];
    __shared__ unsigned h_t[HY][TX];

    const int tid = threadIdx.x;
    const int bx  = blockIdx.x * TX;
    const int by  = blockIdx.y * TY;
    const int b   = blockIdx.z;
    const unsigned base_w = ((unsigned)b << 18);   // word index base for batch

    // Phase 1: load packed bytes, unpack to moment words
    for (int i = tid; i < HY * CHUNKS; i += 256) {
        const int r  = i / CHUNKS;
        const int ci = i - r * CHUNKS;
        const int gy = by + r - 2;
        const int gx = bx + ci * 4 - 4;
        unsigned w = 0;
        if ((unsigned)gy < (unsigned)HH && (unsigned)gx < (unsigned)WW)
            w = g_code4[base_w + ((unsigned)gy << 8) + ((unsigned)gx >> 2)];
        unsigned mc[4], mt[4];
        #pragma unroll
        for (int j = 0; j < 4; ++j) {
            const unsigned byte = (w >> (8 * j)) & 0xFFu;
            const unsigned cv = byte & 0xFu, tv = byte >> 4;
            mc[j] = cv + ((cv * cv) << 8);
            mt[j] = tv + ((tv * tv) << 8);
        }
        const int cc = ci * 4;
        raw_c[r][cc] = mc[0]; raw_c[r][cc+1] = mc[1]; raw_c[r][cc+2] = mc[2]; raw_c[r][cc+3] = mc[3];
        raw_t[r][cc] = mt[0]; raw_t[r][cc+1] = mt[1]; raw_t[r][cc+2] = mt[2]; raw_t[r][cc+3] = mt[3];
    }
    __syncthreads();

    // Phase 2: horizontal 5-sums
    for (int i = tid; i < HY * TX; i += 256) {
        const int r = i >> 6;
        const int c = i & 63;
        h_c[r][c] = raw_c[r][c+2] + raw_c[r][c+3] + raw_c[r][c+4] + raw_c[r][c+5] + raw_c[r][c+6];
        h_t[r][c] = raw_t[r][c+2] + raw_t[r][c+3] + raw_t[r][c+4] + raw_t[r][c+5] + raw_t[r][c+6];
    }
    __syncthreads();

    // Phase 3: vertical sliding 5-window, exact integer variance
    const int c  = tid & 63;
    const int r0 = (tid >> 6) * 8;
    unsigned sc = 0, st = 0;
    #pragma unroll
    for (int d = 0; d < 5; ++d) { sc += h_c[r0 + d][c]; st += h_t[r0 + d][c]; }

    float acc = 0.0f;
    #pragma unroll
    for (int rr = 0; rr < 8; ++rr) {
        const int s1c = (int)(sc & 255u), s2c = (int)(sc >> 8);
        const int s1t = (int)(st & 255u), s2t = (int)(st >> 8);
        const int nump = 25 * s2c - s1c * s1c;   // exactly >= 0
        const int numt = 25 * s2t - s1t * s1t;
        const float d = sqrtf((float)nump * (1.0f / 600.0f))
                      - sqrtf((float)numt * (1.0f / 600.0f));
        acc = fmaf(d, d, acc);
        if (rr < 7) {
            sc += h_c[r0 + rr + 5][c] - h_c[r0 + rr][c];
            st += h_t[r0 + rr + 5][c] - h_t[r0 + rr][c];
        }
    }

    // Reduce
    acc *= (1.0f / NPIX);
    #pragma unroll
    for (int o = 16; o > 0; o >>= 1)
        acc += __shfl_down_sync(0xffffffffu, acc, o);

    __shared__ float warpsum[8];
    if ((tid & 31) == 0) warpsum[tid >> 5] = acc;
    __syncthreads();
    if (tid < 8) {
        float v = warpsum[tid];
        #pragma unroll
        for (int o = 4; o > 0; o >>= 1)
            v += __shfl_down_sync(0xffu, v, o);
        if (tid == 0) atomicAdd(out, v);
    }
}

extern "C" void kernel_launch(void* const* d_in, const int* in_sizes, int n_in,
                              void* d_out, int out_size) {
    const float* pred = (const float*)d_in[0];
    const void*  tgt  = d_in[1];
    float* out = (float*)d_out;

    dcl_init<<<1, 32>>>((const int*)tgt, out);

    const int n_p4_blocks = (BATCH * PIX_PER_B / 4) / 256;   // 8192
    dcl_classify<<<n_p4_blocks, 256>>>(pred, tgt);

    dim3 grid(WW / TX, HH / TY, BATCH);
    dcl_stencil<<<grid, 256>>>(out);
}

// round 5
// speedup vs baseline: 1.3272x; 1.0757x over previous
#include <cuda_runtime.h>

#define BATCH 8
#define NCH   6
#define HH    1024
#define WW    1024
#define TX    64
#define TY    32
#define HX    72      // halo cols: [bx-4, bx+68), 4-aligned
#define HY    36      // halo rows: [by-2, by+34)
#define CHUNKS 18     // HX/4
#define NPIX  (8.0f * 1024.0f * 1024.0f)
#define PIX_PER_B (HH * WW)          // 1<<20
#define CH_STRIDE4 (PIX_PER_B / 4)   // 262144

__device__ unsigned g_code4[(BATCH * PIX_PER_B) / 4];   // 8 MiB: 4 packed bytes/word

// ---- Kernel A: streaming argmax + pack (4 pixels/thread) ----
// Also: per-warp int64/int32 target detection (no separate init kernel) and
// block 0 zeroes the output accumulator (classify fully precedes stencil).
__global__ __launch_bounds__(256) void dcl_classify(
    const float* __restrict__ pred, const void* __restrict__ tgt,
    float* __restrict__ out)
{
    // Detect targets dtype: values in [0,5]; little-endian int64 => odd 32-bit
    // words of the first 64 elements are all zero. For genuine int32 data the
    // odd words are uniform in [0,5]: P(all 32 sampled are 0) = (1/6)^32 ~ 0.
    const int lane = threadIdx.x & 31;
    const int probe = ((const int*)tgt)[2 * lane + 1];
    const int is64 = (__ballot_sync(0xffffffffu, probe != 0) == 0u);

    const unsigned t = blockIdx.x * 256u + threadIdx.x;     // pixel4 index
    if (t == 0) *out = 0.0f;
    const unsigned b   = t >> 18;                           // 2^18 pixel4 / batch
    const unsigned off = t & 0x3FFFFu;

    const float4* pp = (const float4*)pred + (size_t)b * NCH * CH_STRIDE4 + off;
    float4 v[NCH];
    #pragma unroll
    for (int ch = 0; ch < NCH; ++ch) v[ch] = pp[(size_t)ch * CH_STRIDE4];

    int t0, t1, t2, t3;
    if (is64) {
        const int4* tp = (const int4*)tgt + (size_t)t * 2;
        const int4 q0 = tp[0], q1 = tp[1];
        t0 = q0.x; t1 = q0.z; t2 = q1.x; t3 = q1.z;
    } else {
        const int4 q = ((const int4*)tgt)[t];
        t0 = q.x; t1 = q.y; t2 = q.z; t3 = q.w;
    }

    int i0 = 0, i1 = 0, i2 = 0, i3 = 0;
    float m0 = v[0].x, m1 = v[0].y, m2 = v[0].z, m3 = v[0].w;
    #pragma unroll
    for (int ch = 1; ch < NCH; ++ch) {
        if (v[ch].x > m0) { m0 = v[ch].x; i0 = ch; }
        if (v[ch].y > m1) { m1 = v[ch].y; i1 = ch; }
        if (v[ch].z > m2) { m2 = v[ch].z; i2 = ch; }
        if (v[ch].w > m3) { m3 = v[ch].w; i3 = ch; }
    }

    const unsigned b0 = (unsigned)(i0 | (t0 << 4));
    const unsigned b1 = (unsigned)(i1 | (t1 << 4));
    const unsigned b2 = (unsigned)(i2 | (t2 << 4));
    const unsigned b3 = (unsigned)(i3 | (t3 << 4));
    g_code4[t] = b0 | (b1 << 8) | (b2 << 16) | (b3 << 24);
}

// ---- Kernel B: tiled separable 5x5 std stencil + MSE reduce ----
__global__ __launch_bounds__(256) void dcl_stencil(float* __restrict__ out)
{
    // Packed moments: m = v + (v*v << 8). Horizontal 5-sum: s1<=25, s2<=125;
    // vertical 5-sum of those: s1<=125 (8-bit field ok), s2<=625. Exact.
    __shared__ unsigned raw_c[HY][HX];
    __shared__ unsigned raw_t[HY][HX];
    __shared__ unsigned h_c[HY][TX];
    __shared__ unsigned h_t[HY][TX];

    const int tid = threadIdx.x;
    const int bx  = blockIdx.x * TX;
    const int by  = blockIdx.y * TY;
    const int b   = blockIdx.z;
    const unsigned base_w = ((unsigned)b << 18);   // word index base for batch

    // Phase 1: load packed bytes, unpack to moment words
    for (int i = tid; i < HY * CHUNKS; i += 256) {
        const int r  = i / CHUNKS;
        const int ci = i - r * CHUNKS;
        const int gy = by + r - 2;
        const int gx = bx + ci * 4 - 4;
        unsigned w = 0;
        if ((unsigned)gy < (unsigned)HH && (unsigned)gx < (unsigned)WW)
            w = g_code4[base_w + ((unsigned)gy << 8) + ((unsigned)gx >> 2)];
        unsigned mc[4], mt[4];
        #pragma unroll
        for (int j = 0; j < 4; ++j) {
            const unsigned byte = (w >> (8 * j)) & 0xFFu;
            const unsigned cv = byte & 0xFu, tv = byte >> 4;
            mc[j] = cv + ((cv * cv) << 8);
            mt[j] = tv + ((tv * tv) << 8);
        }
        const int cc = ci * 4;
        raw_c[r][cc] = mc[0]; raw_c[r][cc+1] = mc[1]; raw_c[r][cc+2] = mc[2]; raw_c[r][cc+3] = mc[3];
        raw_t[r][cc] = mt[0]; raw_t[r][cc+1] = mt[1]; raw_t[r][cc+2] = mt[2]; raw_t[r][cc+3] = mt[3];
    }
    __syncthreads();

    // Phase 2: horizontal 5-sums
    for (int i = tid; i < HY * TX; i += 256) {
        const int r = i >> 6;
        const int c = i & 63;
        h_c[r][c] = raw_c[r][c+2] + raw_c[r][c+3] + raw_c[r][c+4] + raw_c[r][c+5] + raw_c[r][c+6];
        h_t[r][c] = raw_t[r][c+2] + raw_t[r][c+3] + raw_t[r][c+4] + raw_t[r][c+5] + raw_t[r][c+6];
    }
    __syncthreads();

    // Phase 3: vertical sliding 5-window, exact integer variance
    const int c  = tid & 63;
    const int r0 = (tid >> 6) * 8;
    unsigned sc = 0, st = 0;
    #pragma unroll
    for (int d = 0; d < 5; ++d) { sc += h_c[r0 + d][c]; st += h_t[r0 + d][c]; }

    float acc = 0.0f;
    #pragma unroll
    for (int rr = 0; rr < 8; ++rr) {
        const int s1c = (int)(sc & 255u), s2c = (int)(sc >> 8);
        const int s1t = (int)(st & 255u), s2t = (int)(st >> 8);
        const int nump = 25 * s2c - s1c * s1c;   // exactly >= 0
        const int numt = 25 * s2t - s1t * s1t;
        const float d = sqrtf((float)nump * (1.0f / 600.0f))
                      - sqrtf((float)numt * (1.0f / 600.0f));
        acc = fmaf(d, d, acc);
        if (rr < 7) {
            sc += h_c[r0 + rr + 5][c] - h_c[r0 + rr][c];
            st += h_t[r0 + rr + 5][c] - h_t[r0 + rr][c];
        }
    }

    // Reduce
    acc *= (1.0f / NPIX);
    #pragma unroll
    for (int o = 16; o > 0; o >>= 1)
        acc += __shfl_down_sync(0xffffffffu, acc, o);

    __shared__ float warpsum[8];
    if ((tid & 31) == 0) warpsum[tid >> 5] = acc;
    __syncthreads();
    if (tid < 8) {
        float v = warpsum[tid];
        #pragma unroll
        for (int o = 4; o > 0; o >>= 1)
            v += __shfl_down_sync(0xffu, v, o);
        if (tid == 0) atomicAdd(out, v);
    }
}

extern "C" void kernel_launch(void* const* d_in, const int* in_sizes, int n_in,
                              void* d_out, int out_size) {
    const float* pred = (const float*)d_in[0];
    const void*  tgt  = d_in[1];
    float* out = (float*)d_out;

    const int n_p4_blocks = (BATCH * PIX_PER_B / 4) / 256;   // 8192
    dcl_classify<<<n_p4_blocks, 256>>>(pred, tgt, out);

    dim3 grid(WW / TX, HH / TY, BATCH);
    dcl_stencil<<<grid, 256>>>(out);
}

// round 6
// speedup vs baseline: 1.4115x; 1.0635x over previous
#include <cuda_runtime.h>

#define BATCH 8
#define NCH   6
#define HH    1024
#define WW    1024
#define TX    64
#define TY    32
#define HY    36      // halo rows: [by-2, by+34)
#define NPIX  (8.0f * 1024.0f * 1024.0f)
#define PIX_PER_B (HH * WW)          // 1<<20
#define CH_STRIDE4 (PIX_PER_B / 4)   // 262144

__device__ unsigned g_code4[(BATCH * PIX_PER_B) / 4];   // 8 MiB: 4 packed bytes/word

// ---- Kernel A: streaming argmax + pack (4 pixels/thread) ----
// Per-warp int64/int32 target detection; thread 0 zeroes the accumulator.
__global__ __launch_bounds__(256) void dcl_classify(
    const float* __restrict__ pred, const void* __restrict__ tgt,
    float* __restrict__ out)
{
    // Targets in [0,5]; little-endian int64 => odd 32-bit words of the first
    // 64 elements all zero. P(false positive for int32) = (1/6)^32 ~ 0.
    const int lane = threadIdx.x & 31;
    const int probe = ((const int*)tgt)[2 * lane + 1];
    const int is64 = (__ballot_sync(0xffffffffu, probe != 0) == 0u);

    const unsigned t = blockIdx.x * 256u + threadIdx.x;     // pixel4 index
    if (t == 0) *out = 0.0f;
    const unsigned b   = t >> 18;
    const unsigned off = t & 0x3FFFFu;

    const float4* pp = (const float4*)pred + (size_t)b * NCH * CH_STRIDE4 + off;
    float4 v[NCH];
    #pragma unroll
    for (int ch = 0; ch < NCH; ++ch) v[ch] = pp[(size_t)ch * CH_STRIDE4];

    int t0, t1, t2, t3;
    if (is64) {
        const int4* tp = (const int4*)tgt + (size_t)t * 2;
        const int4 q0 = tp[0], q1 = tp[1];
        t0 = q0.x; t1 = q0.z; t2 = q1.x; t3 = q1.z;
    } else {
        const int4 q = ((const int4*)tgt)[t];
        t0 = q.x; t1 = q.y; t2 = q.z; t3 = q.w;
    }

    int i0 = 0, i1 = 0, i2 = 0, i3 = 0;
    float m0 = v[0].x, m1 = v[0].y, m2 = v[0].z, m3 = v[0].w;
    #pragma unroll
    for (int ch = 1; ch < NCH; ++ch) {
        if (v[ch].x > m0) { m0 = v[ch].x; i0 = ch; }
        if (v[ch].y > m1) { m1 = v[ch].y; i1 = ch; }
        if (v[ch].z > m2) { m2 = v[ch].z; i2 = ch; }
        if (v[ch].w > m3) { m3 = v[ch].w; i3 = ch; }
    }

    g_code4[t] = (unsigned)(i0 | (t0 << 4))
               | ((unsigned)(i1 | (t1 << 4)) << 8)
               | ((unsigned)(i2 | (t2 << 4)) << 16)
               | ((unsigned)(i3 | (t3 << 4)) << 24);
}

// Combined 4-field moment of one code byte:
//   m = cv | (cv*cv)<<8 | tv<<16 | (tv*tv)<<24,  cv,tv in [0,5].
// Horizontal 5-sum per field: 25 / 125 / 25 / 125 — no cross-field carry.
__device__ __forceinline__ unsigned moment(unsigned b) {
    const unsigned cv = b & 15u;
    const unsigned tv = b >> 4;
    return cv * ((cv << 8) + 1u) + ((tv * ((tv << 8) + 1u)) << 16);
}

// ---- Kernel B: fused horizontal(gmem->smem) + vertical(smem->reg) stencil ----
__global__ __launch_bounds__(256) void dcl_stencil(float* __restrict__ out)
{
    __shared__ unsigned hbuf[HY][TX];   // combined packed horizontal 5-sums

    const int tid = threadIdx.x;
    const int bx  = blockIdx.x * TX;
    const int by  = blockIdx.y * TY;
    const unsigned base_w = ((unsigned)blockIdx.z << 18);

    // Phase A: horizontal 5-sums straight from global code words.
    // One iteration produces 4 h-outputs (cols gx..gx+3) from code words
    // covering cols gx-4..gx+7 (3 words; zero outside the image = padding).
    for (int i = tid; i < HY * (TX / 4); i += 256) {
        const int r  = i >> 4;          // 0..35  (halo row)
        const int cw = i & 15;          // word-col within tile
        const int gy = by + r - 2;
        unsigned wm = 0, w0 = 0, wp = 0;
        if ((unsigned)gy < (unsigned)HH) {
            const unsigned rowbase = base_w + ((unsigned)gy << 8);
            const int wc = (bx >> 2) + cw;          // 0..255
            if (wc > 0)   wm = g_code4[rowbase + wc - 1];
            w0 = g_code4[rowbase + wc];
            if (wc < 255) wp = g_code4[rowbase + wc + 1];
        }
        // elements gx-2..gx+5: bytes wm.2, wm.3, w0.0-3, wp.0, wp.1
        const unsigned e0 = moment((wm >> 16) & 255u);
        const unsigned e1 = moment(wm >> 24);
        const unsigned e2 = moment(w0 & 255u);
        const unsigned e3 = moment((w0 >> 8) & 255u);
        const unsigned e4 = moment((w0 >> 16) & 255u);
        const unsigned e5 = moment(w0 >> 24);
        const unsigned e6 = moment(wp & 255u);
        const unsigned e7 = moment((wp >> 8) & 255u);

        unsigned s = e0 + e1 + e2 + e3 + e4;
        uint4 o;
        o.x = s; s += e5 - e0;
        o.y = s; s += e6 - e1;
        o.z = s; s += e7 - e2;
        o.w = s;
        *(uint4*)&hbuf[r][cw * 4] = o;
    }
    __syncthreads();

    // Phase B: vertical 5-sums in registers; 4 cols x 2 rows per thread.
    const int cg = (tid & 15) * 4;      // column base
    const int r0 = (tid >> 4) * 2;      // output row base (0..30)

    uint4 rv[6];
    #pragma unroll
    for (int d = 0; d < 6; ++d)
        rv[d] = *(const uint4*)&hbuf[r0 + d][cg];

    float acc = 0.0f;
    #pragma unroll
    for (int rr = 0; rr < 2; ++rr) {
        #pragma unroll
        for (int j = 0; j < 4; ++j) {
            unsigned sc = 0, st = 0;
            #pragma unroll
            for (int d = 0; d < 5; ++d) {
                const unsigned w = (&rv[rr + d].x)[j];
                sc += w & 0xFFFFu;      // cv-sum | cv2-sum<<8
                st += w >> 16;          // tv-sum | tv2-sum<<8
            }
            // vertical: s1<=125 confined to bits 0-7; s2<=625 in bits 8+.
            const int s1c = (int)(sc & 255u), s2c = (int)(sc >> 8);
            const int s1t = (int)(st & 255u), s2t = (int)(st >> 8);
            const int nump = 25 * s2c - s1c * s1c;   // exact, >= 0
            const int numt = 25 * s2t - s1t * s1t;
            const float d = sqrtf((float)nump * (1.0f / 600.0f))
                          - sqrtf((float)numt * (1.0f / 600.0f));
            acc = fmaf(d, d, acc);
        }
    }

    // Reduce: warp shuffle -> smem -> one atomic per block.
    acc *= (1.0f / NPIX);
    #pragma unroll
    for (int o = 16; o > 0; o >>= 1)
        acc += __shfl_down_sync(0xffffffffu, acc, o);

    __shared__ float warpsum[8];
    if ((tid & 31) == 0) warpsum[tid >> 5] = acc;
    __syncthreads();
    if (tid < 8) {
        float v = warpsum[tid];
        #pragma unroll
        for (int o = 4; o > 0; o >>= 1)
            v += __shfl_down_sync(0xffu, v, o);
        if (tid == 0) atomicAdd(out, v);
    }
}

extern "C" void kernel_launch(void* const* d_in, const int* in_sizes, int n_in,
                              void* d_out, int out_size) {
    const float* pred = (const float*)d_in[0];
    const void*  tgt  = d_in[1];
    float* out = (float*)d_out;

    const int n_p4_blocks = (BATCH * PIX_PER_B / 4) / 256;   // 8192
    dcl_classify<<<n_p4_blocks, 256>>>(pred, tgt, out);

    dim3 grid(WW / TX, HH / TY, BATCH);
    dcl_stencil<<<grid, 256>>>(out);
}

// round 7
// speedup vs baseline: 1.5868x; 1.1242x over previous
#include <cuda_runtime.h>

#define BATCH 8
#define NCH   6
#define HH    1024
#define WW    1024
#define TX    64
#define TY    64
#define HY    68      // halo rows: [by-2, by+66)
#define NPIX  (8.0f * 1024.0f * 1024.0f)
#define PIX_PER_B (HH * WW)          // 1<<20
#define CH_STRIDE4 (PIX_PER_B / 4)   // 262144

__device__ unsigned g_code4[(BATCH * PIX_PER_B) / 4];   // 8 MiB: 4 packed bytes/word

// ---- Kernel A: streaming argmax + pack (4 pixels/thread) ----
__global__ __launch_bounds__(256) void dcl_classify(
    const float* __restrict__ pred, const void* __restrict__ tgt,
    float* __restrict__ out)
{
    // Targets in [0,5]; little-endian int64 => odd 32-bit words of the first
    // 64 elements all zero. P(false positive for int32) = (1/6)^32 ~ 0.
    const int lane = threadIdx.x & 31;
    const int probe = ((const int*)tgt)[2 * lane + 1];
    const int is64 = (__ballot_sync(0xffffffffu, probe != 0) == 0u);

    const unsigned t = blockIdx.x * 256u + threadIdx.x;     // pixel4 index
    if (t == 0) *out = 0.0f;
    const unsigned b   = t >> 18;
    const unsigned off = t & 0x3FFFFu;

    const float4* pp = (const float4*)pred + (size_t)b * NCH * CH_STRIDE4 + off;
    float4 v[NCH];
    #pragma unroll
    for (int ch = 0; ch < NCH; ++ch) v[ch] = pp[(size_t)ch * CH_STRIDE4];

    int t0, t1, t2, t3;
    if (is64) {
        const int4* tp = (const int4*)tgt + (size_t)t * 2;
        const int4 q0 = tp[0], q1 = tp[1];
        t0 = q0.x; t1 = q0.z; t2 = q1.x; t3 = q1.z;
    } else {
        const int4 q = ((const int4*)tgt)[t];
        t0 = q.x; t1 = q.y; t2 = q.z; t3 = q.w;
    }

    int i0 = 0, i1 = 0, i2 = 0, i3 = 0;
    float m0 = v[0].x, m1 = v[0].y, m2 = v[0].z, m3 = v[0].w;
    #pragma unroll
    for (int ch = 1; ch < NCH; ++ch) {
        if (v[ch].x > m0) { m0 = v[ch].x; i0 = ch; }
        if (v[ch].y > m1) { m1 = v[ch].y; i1 = ch; }
        if (v[ch].z > m2) { m2 = v[ch].z; i2 = ch; }
        if (v[ch].w > m3) { m3 = v[ch].w; i3 = ch; }
    }

    g_code4[t] = (unsigned)(i0 | (t0 << 4))
               | ((unsigned)(i1 | (t1 << 4)) << 8)
               | ((unsigned)(i2 | (t2 << 4)) << 16)
               | ((unsigned)(i3 | (t3 << 4)) << 24);
}

// ---- Kernel B: stencil + MSE reduce ----
// hbuf[r][c] = uint2{ a, b } with 16-bit fields:
//   a = h5sum(cv)  | h5sum(tv)  << 16   (each <= 25)
//   b = h5sum(cv2) | h5sum(tv2) << 16   (each <= 125)
// Vertical 5-sums: a-fields <= 125, b-fields <= 625 — no carry.
__global__ __launch_bounds__(512) void dcl_stencil(float* __restrict__ out)
{
    __shared__ uint2 hbuf[HY][TX];   // 34.8 KB

    const int tid = threadIdx.x;
    const int bx  = blockIdx.x * TX;
    const int by  = blockIdx.y * TY;
    const unsigned base_w = ((unsigned)blockIdx.z << 18);

    // ---- Phase A: horizontal 5-sums straight from global code words ----
    for (int i = tid; i < HY * (TX / 4); i += 512) {
        const int r  = i >> 4;          // halo row 0..67
        const int cw = i & 15;          // word-col within tile
        const int gy = by + r - 2;
        unsigned wm = 0, w0 = 0, wp = 0;
        if ((unsigned)gy < (unsigned)HH) {
            const unsigned rowbase = base_w + ((unsigned)gy << 8);
            const int wc = (bx >> 2) + cw;          // 0..255
            if (wc > 0)   wm = g_code4[rowbase + wc - 1];
            w0 = g_code4[rowbase + wc];
            if (wc < 255) wp = g_code4[rowbase + wc + 1];
        }
        // code bytes covering cols gx-2..gx+5
        unsigned e[8];
        e[0] = (wm >> 16) & 255u;  e[1] = wm >> 24;
        e[2] =  w0        & 255u;  e[3] = (w0 >> 8) & 255u;
        e[4] = (w0 >> 16) & 255u;  e[5] =  w0 >> 24;
        e[6] =  wp        & 255u;  e[7] = (wp >> 8) & 255u;
        unsigned ma[8], mb[8];
        #pragma unroll
        for (int j = 0; j < 8; ++j) {
            const unsigned cv = e[j] & 15u, tv = e[j] >> 4;
            ma[j] = cv + (tv << 16);
            mb[j] = cv * cv + ((tv * tv) << 16);
        }
        unsigned sa = ma[0] + ma[1] + ma[2] + ma[3] + ma[4];
        unsigned sb = mb[0] + mb[1] + mb[2] + mb[3] + mb[4];
        uint4 lo, hi;
        lo.x = sa; lo.y = sb; sa += ma[5] - ma[0]; sb += mb[5] - mb[0];
        lo.z = sa; lo.w = sb; sa += ma[6] - ma[1]; sb += mb[6] - mb[1];
        hi.x = sa; hi.y = sb; sa += ma[7] - ma[2]; sb += mb[7] - mb[2];
        hi.z = sa; hi.w = sb;
        uint4* dst = (uint4*)&hbuf[r][cw * 4];
        dst[0] = lo; dst[1] = hi;
    }
    __syncthreads();

    // ---- Phase B: vertical sliding 5-window, 1 col x 8 rows per thread ----
    const int c  = tid & 63;
    const int r0 = (tid >> 6) * 8;

    unsigned a[12], b[12];
    #pragma unroll
    for (int d = 0; d < 12; ++d) {
        const uint2 w = hbuf[r0 + d][c];
        a[d] = w.x; b[d] = w.y;
    }
    unsigned sa = a[0] + a[1] + a[2] + a[3] + a[4];
    unsigned sb = b[0] + b[1] + b[2] + b[3] + b[4];

    int   acc_i = 0;
    float acc_s = 0.0f;
    #pragma unroll
    for (int rr = 0; rr < 8; ++rr) {
        const int s1c = (int)(sa & 0xFFFFu), s1t = (int)(sa >> 16);
        const int s2c = (int)(sb & 0xFFFFu), s2t = (int)(sb >> 16);
        const int np = 25 * s2c - s1c * s1c;   // exact, in [0, 15625]
        const int nt = 25 * s2t - s1t * s1t;
        acc_i += np + nt;
        // (sqrt(np/600)-sqrt(nt/600))^2 = (np + nt - 2*sqrt(np*nt))/600
        const float p = (float)(np * nt);      // <= 2.44e8 < 2^31
        float s;
        asm("sqrt.approx.f32 %0, %1;" : "=f"(s) : "f"(p));
        acc_s += s;
        if (rr < 7) { sa += a[rr + 5] - a[rr]; sb += b[rr + 5] - b[rr]; }
    }

    float acc = fmaf(-2.0f, acc_s, (float)acc_i) * (1.0f / (600.0f * NPIX));

    // ---- Reduce: warp shuffle -> smem -> one atomic per block ----
    #pragma unroll
    for (int o = 16; o > 0; o >>= 1)
        acc += __shfl_down_sync(0xffffffffu, acc, o);

    __shared__ float warpsum[16];
    if ((tid & 31) == 0) warpsum[tid >> 5] = acc;
    __syncthreads();
    if (tid < 16) {
        float v = warpsum[tid];
        #pragma unroll
        for (int o = 8; o > 0; o >>= 1)
            v += __shfl_down_sync(0xffffu, v, o);
        if (tid == 0) atomicAdd(out, v);
    }
}

extern "C" void kernel_launch(void* const* d_in, const int* in_sizes, int n_in,
                              void* d_out, int out_size) {
    const float* pred = (const float*)d_in[0];
    const void*  tgt  = d_in[1];
    float* out = (float*)d_out;

    const int n_p4_blocks = (BATCH * PIX_PER_B / 4) / 256;   // 8192
    dcl_classify<<<n_p4_blocks, 256>>>(pred, tgt, out);

    dim3 grid(WW / TX, HH / TY, BATCH);
    dcl_stencil<<<grid, 512>>>(out);
}